// round 2
// baseline (speedup 1.0000x reference)
#include <cuda_runtime.h>
#include <math.h>

#define N_BODY 512
#define NV 6890
#define NJ 24
#define NP 207

typedef unsigned long long ull;

__device__ __constant__ int d_parents[NJ] =
    {0, 0, 0, 0, 1, 2, 3, 4, 5, 6, 7, 8, 9, 9, 9, 12, 13, 14, 16, 17, 18, 19, 20, 21};

// ---------------- scratch (device globals; no allocations) ----------------
__device__ float g_JT[NJ * 3];
__device__ float g_JS[NJ * 30];
__device__ float g_jregT[NJ * NV];
__device__ float g_lrotT[NP * N_BODY];    // lrotmin transposed [p][n]
__device__ float g_GT[NJ * 12 * N_BODY];  // G' transposed [j*12+e][n]
__device__ float g_betasT[10 * N_BODY];
__device__ float g_transT[3 * N_BODY];

// ---------------- f32x2 helpers (FFMA2 is PTX-only) ----------------
__device__ __forceinline__ ull pk2(float a, float b) {
    ull r;
    asm("mov.b64 %0, {%1, %2};" : "=l"(r) : "f"(a), "f"(b));
    return r;
}
__device__ __forceinline__ void upk2(float& a, float& b, ull v) {
    asm("mov.b64 {%0, %1}, %2;" : "=f"(a), "=f"(b) : "l"(v));
}
__device__ __forceinline__ ull fma2_(ull a, ull b, ull c) {
    ull d;
    asm("fma.rn.f32x2 %0, %1, %2, %3;" : "=l"(d) : "l"(a), "l"(b), "l"(c));
    return d;
}

// ---------------- kernel 1: reduce J_regressor against template/shapedirs ----------------
__global__ void k_pre(const float* __restrict__ Jreg,
                      const float* __restrict__ vt,
                      const float* __restrict__ sd) {
    int j = blockIdx.x;
    float acc[33];
#pragma unroll
    for (int i = 0; i < 33; i++) acc[i] = 0.f;
    for (int v = threadIdx.x; v < NV; v += blockDim.x) {
        float r = Jreg[j * NV + v];
#pragma unroll
        for (int c = 0; c < 3; c++) acc[c] += r * vt[v * 3 + c];
#pragma unroll
        for (int i = 0; i < 30; i++) acc[3 + i] += r * sd[v * 30 + i];
    }
    __shared__ float red[256];
    for (int i = 0; i < 33; i++) {
        red[threadIdx.x] = acc[i];
        __syncthreads();
        for (int s = 128; s > 0; s >>= 1) {
            if (threadIdx.x < s) red[threadIdx.x] += red[threadIdx.x + s];
            __syncthreads();
        }
        if (threadIdx.x == 0) {
            if (i < 3) g_JT[j * 3 + i] = red[0];
            else       g_JS[j * 30 + (i - 3)] = red[0];
        }
        __syncthreads();
    }
}

// ---------------- kernel 2: transpose joint_regressor ----------------
__global__ void k_jregT(const float* __restrict__ jreg) {
    int v = blockIdx.x * blockDim.x + threadIdx.x;
    if (v < NV) {
#pragma unroll
        for (int j = 0; j < NJ; j++) g_jregT[j * NV + v] = jreg[v * NJ + j];
    }
}

// ---------------- kernel 3: per-body rodrigues + FK + lrotmin ----------------
__global__ void k_body(const float* __restrict__ betas,
                       const float* __restrict__ thetas,
                       const float* __restrict__ trans) {
    int n = blockIdx.x;
    int lane = threadIdx.x;
    __shared__ float sR[NJ][9];
    __shared__ float sJ[NJ][3];
    __shared__ float sT[NJ][3];
    __shared__ float sG[NJ][12];

    if (lane < NJ) {
        int j = lane;
        float b[10];
#pragma unroll
        for (int k = 0; k < 10; k++) b[k] = betas[n * 10 + k];
#pragma unroll
        for (int c = 0; c < 3; c++) {
            float a = g_JT[j * 3 + c];
#pragma unroll
            for (int k = 0; k < 10; k++) a += g_JS[j * 30 + c * 10 + k] * b[k];
            sJ[j][c] = a;
        }
        float rx = thetas[n * 72 + j * 3 + 0];
        float ry = thetas[n * 72 + j * 3 + 1];
        float rz = thetas[n * 72 + j * 3 + 2];
        float th = sqrtf(rx * rx + ry * ry + rz * rz) + 1e-8f;
        float inv = 1.0f / th;
        float x = rx * inv, y = ry * inv, z = rz * inv;
        float ct = cosf(th), st = sinf(th), oc = 1.0f - ct;
        sR[j][0] = ct + oc * x * x;      sR[j][1] = oc * x * y - st * z;  sR[j][2] = oc * x * z + st * y;
        sR[j][3] = oc * y * x + st * z;  sR[j][4] = ct + oc * y * y;      sR[j][5] = oc * y * z - st * x;
        sR[j][6] = oc * z * x - st * y;  sR[j][7] = oc * z * y + st * x;  sR[j][8] = ct + oc * z * z;
    }
    __syncwarp();
    if (lane < NJ) {
        int j = lane;
        if (j == 0) {
#pragma unroll
            for (int c = 0; c < 3; c++) sT[0][c] = sJ[0][c];
        } else {
            int p = d_parents[j];
#pragma unroll
            for (int c = 0; c < 3; c++) sT[j][c] = sJ[j][c] - sJ[p][c];
        }
    }
    __syncwarp();
    if (lane == 0) {
#pragma unroll
        for (int r = 0; r < 3; r++) {
            sG[0][r * 4 + 0] = sR[0][r * 3 + 0];
            sG[0][r * 4 + 1] = sR[0][r * 3 + 1];
            sG[0][r * 4 + 2] = sR[0][r * 3 + 2];
            sG[0][r * 4 + 3] = sT[0][r];
        }
        for (int j = 1; j < NJ; j++) {
            int p = d_parents[j];
            float Rn[9], tn[3];
#pragma unroll
            for (int r = 0; r < 3; r++) {
#pragma unroll
                for (int c = 0; c < 3; c++) {
                    Rn[r * 3 + c] = sG[p][r * 4 + 0] * sR[j][0 * 3 + c]
                                  + sG[p][r * 4 + 1] * sR[j][1 * 3 + c]
                                  + sG[p][r * 4 + 2] * sR[j][2 * 3 + c];
                }
                tn[r] = sG[p][r * 4 + 3]
                      + sG[p][r * 4 + 0] * sT[j][0]
                      + sG[p][r * 4 + 1] * sT[j][1]
                      + sG[p][r * 4 + 2] * sT[j][2];
            }
#pragma unroll
            for (int r = 0; r < 3; r++) {
                sG[j][r * 4 + 0] = Rn[r * 3 + 0];
                sG[j][r * 4 + 1] = Rn[r * 3 + 1];
                sG[j][r * 4 + 2] = Rn[r * 3 + 2];
                sG[j][r * 4 + 3] = tn[r];
            }
        }
    }
    __syncwarp();
    if (lane < NJ) {
        int j = lane;
        float t0 = sG[j][3]  - (sG[j][0] * sJ[j][0] + sG[j][1] * sJ[j][1] + sG[j][2]  * sJ[j][2]);
        float t1 = sG[j][7]  - (sG[j][4] * sJ[j][0] + sG[j][5] * sJ[j][1] + sG[j][6]  * sJ[j][2]);
        float t2 = sG[j][11] - (sG[j][8] * sJ[j][0] + sG[j][9] * sJ[j][1] + sG[j][10] * sJ[j][2]);
        sG[j][3] = t0; sG[j][7] = t1; sG[j][11] = t2;
    }
    __syncwarp();
    for (int idx = lane; idx < NJ * 12; idx += 32)
        g_GT[idx * N_BODY + n] = sG[idx / 12][idx % 12];
    for (int idx = lane; idx < NP; idx += 32) {
        int j = idx / 9 + 1;
        int e = idx % 9;
        float v = sR[j][e];
        if (e == 0 || e == 4 || e == 8) v -= 1.0f;
        g_lrotT[idx * N_BODY + n] = v;
    }
    if (lane < 10) g_betasT[lane * N_BODY + n] = betas[n * 10 + lane];
    if (lane < 3)  g_transT[lane * N_BODY + n] = trans[n * 3 + lane];
}

// ---------------- kernel 4: fused shape+pose blend + LBS (f32x2) ----------------
// tile: 32 bodies x 16 verts, 128 threads: thread = 1 body x 4 verts (2 pairs)
#define TN 32
#define TV 16
#define PCH 69   // 207 = 3*69 p-chunks
#define RS 52    // smem row stride for pd chunk (floats): 4-way STS conflict, 16B-aligned LDS.128

// smem layout (floats):
//   [0, 6624)        lrot_s  [p][nl]                (reused later: sG 288x32=9216 spans [0,9216), sOut [0,1568))
//   [6624, 10212)    pd_s    chunk [pl][RS]
//   [10212, 10596)   w_s     [vl][24]
//   [10596, 11076)   sd_s    [vl][30]
//   [11076, 11124)   vt_s    [vl][3]
#define OFF_PD  6624
#define OFF_W   10212
#define OFF_SD  10596
#define OFF_VT  11076
#define SM_FLOATS 11124

__global__ void __launch_bounds__(128) k_main(const float* __restrict__ vt,
                                              const float* __restrict__ sd,
                                              const float* __restrict__ pd,
                                              const float* __restrict__ w,
                                              float* __restrict__ out) {
    extern __shared__ float sm[];
    float* lrot_s = sm;
    float* pd_s   = sm + OFF_PD;
    float* w_s    = sm + OFF_W;
    float* sd_s   = sm + OFF_SD;
    float* vt_s   = sm + OFF_VT;

    int tid = threadIdx.x;
    int vbase = blockIdx.x * TV;
    int nbase = blockIdx.y * TN;

    // ---- cooperative loads ----
    for (int i = tid; i < NP * TN; i += 128) {
        int p = i >> 5, nl = i & 31;
        lrot_s[i] = g_lrotT[p * N_BODY + nbase + nl];
    }
    for (int i = tid; i < TV * 24; i += 128) {
        int vl = i / 24, j = i % 24;
        int v = vbase + vl;
        w_s[i] = (v < NV) ? w[v * 24 + j] : 0.f;
    }
    for (int i = tid; i < TV * 30; i += 128) {
        int vl = i / 30, f = i % 30;
        int v = vbase + vl;
        sd_s[i] = (v < NV) ? sd[v * 30 + f] : 0.f;
    }
    for (int i = tid; i < TV * 3; i += 128) {
        int vl = i / 3, c = i % 3;
        int v = vbase + vl;
        vt_s[i] = (v < NV) ? vt[v * 3 + c] : 0.f;
    }
    __syncthreads();

    int nl = tid & 31;
    int vg = tid >> 5;         // 0..3, my 4 verts = vbase + vg*4 .. +4
    int n = nbase + nl;

    // ---- shape blend init: acc[c][pair] packed over vertex pairs ----
    float b[10];
#pragma unroll
    for (int k = 0; k < 10; k++) b[k] = g_betasT[k * N_BODY + n];

    ull acc[3][2];
#pragma unroll
    for (int pr = 0; pr < 2; pr++) {
#pragma unroll
        for (int c = 0; c < 3; c++) {
            float a0, a1;
            int vl0 = vg * 4 + pr * 2;
            a0 = vt_s[vl0 * 3 + c];
            a1 = vt_s[(vl0 + 1) * 3 + c];
#pragma unroll
            for (int k = 0; k < 10; k++) {
                a0 += b[k] * sd_s[vl0 * 30 + c * 10 + k];
                a1 += b[k] * sd_s[(vl0 + 1) * 30 + c * 10 + k];
            }
            acc[c][pr] = pk2(a0, a1);
        }
    }

    // ---- pose blend over 3 p-chunks ----
    const ulonglong2* pd2 = reinterpret_cast<const ulonglong2*>(pd_s);
    for (int ch = 0; ch < 3; ch++) {
        int pbase = ch * PCH;
        if (ch) __syncthreads();
        // load chunk: gmem coalesced along p, smem transposed to v-fastest
        for (int i = tid; i < PCH * 48; i += 128) {
            int pl = i % PCH;
            int r = i / PCH;          // r = vl*3 + c
            int vl = r / 3, c = r % 3;
            int v = vbase + vl;
            pd_s[pl * RS + c * 16 + vl] =
                (v < NV) ? pd[(size_t)v * 621 + c * 207 + pbase + pl] : 0.f;
        }
        __syncthreads();
#pragma unroll 4
        for (int pl = 0; pl < PCH; pl++) {
            float lr = lrot_s[(pbase + pl) * TN + nl];
            ull lr2 = pk2(lr, lr);
#pragma unroll
            for (int c = 0; c < 3; c++) {
                ulonglong2 q = pd2[pl * (RS / 4) + c * 4 + vg];
                acc[c][0] = fma2_(lr2, q.x, acc[c][0]);
                acc[c][1] = fma2_(lr2, q.y, acc[c][1]);
            }
        }
    }

    // ---- stage G' slice into smem (reuse lrot/pd region) ----
    __syncthreads();
    float* sG = sm;   // 288 * 32 floats
    for (int i = tid; i < NJ * 12 * TN; i += 128)
        sG[i] = g_GT[(i >> 5) * N_BODY + nbase + (i & 31)];
    __syncthreads();

    // ---- skinning (packed over vertex pairs) ----
    ull outa[3][2];
#pragma unroll
    for (int c = 0; c < 3; c++) {
        float t = g_transT[c * N_BODY + n];
        outa[c][0] = pk2(t, t);
        outa[c][1] = outa[c][0];
    }
#pragma unroll 1
    for (int j = 0; j < NJ; j++) {
        ull g2[12];
#pragma unroll
        for (int e = 0; e < 12; e++) {
            float ge = sG[(j * 12 + e) * TN + nl];
            g2[e] = pk2(ge, ge);
        }
#pragma unroll
        for (int pr = 0; pr < 2; pr++) {
            ull vx = acc[0][pr], vy = acc[1][pr], vz = acc[2][pr];
            ull tx = fma2_(g2[0], vx, fma2_(g2[1], vy, fma2_(g2[2],  vz, g2[3])));
            ull ty = fma2_(g2[4], vx, fma2_(g2[5], vy, fma2_(g2[6],  vz, g2[7])));
            ull tz = fma2_(g2[8], vx, fma2_(g2[9], vy, fma2_(g2[10], vz, g2[11])));
            int vl0 = vg * 4 + pr * 2;
            ull w2 = pk2(w_s[vl0 * 24 + j], w_s[(vl0 + 1) * 24 + j]);
            outa[0][pr] = fma2_(w2, tx, outa[0][pr]);
            outa[1][pr] = fma2_(w2, ty, outa[1][pr]);
            outa[2][pr] = fma2_(w2, tz, outa[2][pr]);
        }
    }

    // ---- stage output through smem for coalesced stores ----
    __syncthreads();               // everyone done reading sG
    float* sOut = sm;              // [32][49] (pad 49 -> conflict-free STS)
#pragma unroll
    for (int pr = 0; pr < 2; pr++) {
        int vl0 = vg * 4 + pr * 2;
#pragma unroll
        for (int c = 0; c < 3; c++) {
            float a0, a1;
            upk2(a0, a1, outa[c][pr]);
            sOut[nl * 49 + vl0 * 3 + c] = a0;
            sOut[nl * 49 + (vl0 + 1) * 3 + c] = a1;
        }
    }
    __syncthreads();
    int flim = (NV - vbase) * 3;
    if (flim > 48) flim = 48;
    for (int i = tid; i < TN * 48; i += 128) {
        int nr = i / 48, f = i % 48;
        if (f < flim)
            out[(size_t)(nbase + nr) * (NV * 3) + (size_t)vbase * 3 + f] = sOut[nr * 49 + f];
    }
}

// ---------------- kernel 5: joint regression of the result ----------------
__global__ void __launch_bounds__(256) k_joints(const float* __restrict__ res,
                                                float* __restrict__ jout) {
    int n = blockIdx.x;
    int tid = threadIdx.x;
    float acc[72];
#pragma unroll
    for (int i = 0; i < 72; i++) acc[i] = 0.f;
    for (int v = tid; v < NV; v += 256) {
        size_t o = ((size_t)n * NV + v) * 3;
        float r0 = res[o + 0], r1 = res[o + 1], r2 = res[o + 2];
#pragma unroll
        for (int j = 0; j < NJ; j++) {
            float jr = g_jregT[j * NV + v];
            acc[j * 3 + 0] += jr * r0;
            acc[j * 3 + 1] += jr * r1;
            acc[j * 3 + 2] += jr * r2;
        }
    }
#pragma unroll
    for (int i = 0; i < 72; i++) {
#pragma unroll
        for (int off = 16; off > 0; off >>= 1)
            acc[i] += __shfl_down_sync(0xffffffff, acc[i], off);
    }
    __shared__ float red[8][72];
    int wid = tid >> 5, lanei = tid & 31;
    if (lanei == 0) {
#pragma unroll
        for (int i = 0; i < 72; i++) red[wid][i] = acc[i];
    }
    __syncthreads();
    if (tid < 72) {
        float s = 0.f;
#pragma unroll
        for (int wq = 0; wq < 8; wq++) s += red[wq][tid];
        jout[n * 72 + tid] = s;
    }
}

// ---------------- launch ----------------
extern "C" void kernel_launch(void* const* d_in, const int* in_sizes, int n_in,
                              void* d_out, int out_size) {
    const float* betas  = (const float*)d_in[0];
    const float* thetas = (const float*)d_in[1];
    const float* trans  = (const float*)d_in[2];
    const float* vt     = (const float*)d_in[3];
    const float* sd     = (const float*)d_in[4];
    const float* pd     = (const float*)d_in[5];
    const float* Jreg   = (const float*)d_in[6];
    const float* jreg   = (const float*)d_in[7];
    const float* w      = (const float*)d_in[8];
    float* out  = (float*)d_out;
    float* jout = out + (size_t)N_BODY * NV * 3;

    k_pre<<<NJ, 256>>>(Jreg, vt, sd);
    k_jregT<<<(NV + 255) / 256, 256>>>(jreg);
    k_body<<<N_BODY, 32>>>(betas, thetas, trans);

    const int SMEM = SM_FLOATS * (int)sizeof(float);
    cudaFuncSetAttribute(k_main, cudaFuncAttributeMaxDynamicSharedMemorySize, SMEM);
    dim3 grid((NV + TV - 1) / TV, N_BODY / TN);
    k_main<<<grid, 128, SMEM>>>(vt, sd, pd, w, out);

    k_joints<<<N_BODY, 256>>>(out, jout);
}